// round 2
// baseline (speedup 1.0000x reference)
#include <cuda_runtime.h>
#include <math.h>

#define KTAGS 64
#define DDIM  128
#define VWORDS 50000
#define NV   (VWORDS + 2)
#define BATCHN 2048
#define TLEN 256
#define BOS_TAG 63
#define EOS_TAG 62
#define TINYV 1e-45f

#define NWARP 4          // warps per scan CTA
#define SPW   4          // sentences per warp
#define SPB   (NWARP * SPW)   // 16 sentences per CTA
#define ASTR  68         // padded alpha stride (floats)
#define WSTR  257        // padded word stride (ints)

typedef unsigned long long u64;

__device__ __forceinline__ u64 pack2(float lo, float hi) {
    u64 r; asm("mov.b64 %0,{%1,%2};" : "=l"(r) : "f"(lo), "f"(hi)); return r;
}
__device__ __forceinline__ u64 fma2(u64 a, u64 b, u64 c) {
    u64 d; asm("fma.rn.f32x2 %0,%1,%2,%3;" : "=l"(d) : "l"(a), "l"(b), "l"(c)); return d;
}
__device__ __forceinline__ u64 mul2(u64 a, u64 b) {
    u64 d; asm("mul.rn.f32x2 %0,%1,%2;" : "=l"(d) : "l"(a), "l"(b)); return d;
}
__device__ __forceinline__ float2 unpack2(u64 v) {
    float2 f; asm("mov.b64 {%0,%1},%2;" : "=f"(f.x), "=f"(f.y) : "l"(v)); return f;
}

// Scratch (static device globals; no dynamic allocation)
__device__ float g_A[KTAGS * KTAGS];               // A' = exp(WA)/64, col BOS zeroed
__device__ float g_Bt[(size_t)NV * KTAGS];         // emission table, word-major [w][k]

// ---------------------------------------------------------------------------
// Kernel 1: A'[i][j] = exp(WA[i][j]) / 64, A'[:,BOS] = 0
// ---------------------------------------------------------------------------
__global__ void prep_A_kernel(const float* __restrict__ WA) {
    int idx = blockIdx.x * blockDim.x + threadIdx.x;
    if (idx < KTAGS * KTAGS) {
        int j = idx & (KTAGS - 1);
        g_A[idx] = (j == BOS_TAG) ? 0.0f : expf(WA[idx]) * (1.0f / 64.0f);
    }
}

// ---------------------------------------------------------------------------
// Kernel 2: emission table g_Bt[w][k] = exp(dot(ThetaB[k,:], E[w,:]))
// f32x2-packed accumulate; tags EOS/BOS forced to TINY.
// ---------------------------------------------------------------------------
__global__ __launch_bounds__(256) void emit_table_kernel(
        const float* __restrict__ ThetaB, const float* __restrict__ E) {
    __shared__ __align__(16) float sE[64 * 65];
    __shared__ __align__(16) float sTh[64 * ASTR];   // [d_local][k]

    int tid = threadIdx.x;
    int wq  = tid & 15;    // word quad
    int kq  = tid >> 4;    // tag quad
    int w0  = blockIdx.x * 64;

    u64 acc[4][2];         // [word][pair of 2 tags]
#pragma unroll
    for (int a = 0; a < 4; a++) { acc[a][0] = 0ull; acc[a][1] = 0ull; }

    for (int dc = 0; dc < 2; dc++) {
        for (int idx = tid; idx < 64 * 64; idx += 256) {
            int k = idx >> 6, dl = idx & 63;
            sTh[dl * ASTR + k] = ThetaB[k * DDIM + dc * 64 + dl];
        }
        for (int idx = tid; idx < 64 * 64; idx += 256) {
            int w = idx >> 6, dl = idx & 63;
            int wg = w0 + w;
            sE[w * 65 + dl] = (wg < NV) ? E[(size_t)wg * DDIM + dc * 64 + dl] : 0.0f;
        }
        __syncthreads();

#pragma unroll 8
        for (int dl = 0; dl < 64; dl++) {
            ulonglong2 th = *(const ulonglong2*)&sTh[dl * ASTR + kq * 4];
#pragma unroll
            for (int ww = 0; ww < 4; ww++) {
                float e = sE[(wq * 4 + ww) * 65 + dl];
                u64 ep = pack2(e, e);
                acc[ww][0] = fma2(ep, th.x, acc[ww][0]);
                acc[ww][1] = fma2(ep, th.y, acc[ww][1]);
            }
        }
        __syncthreads();
    }

#pragma unroll
    for (int ww = 0; ww < 4; ww++) {
        int w = w0 + wq * 4 + ww;
        if (w < NV) {
            float2 p0 = unpack2(acc[ww][0]);
            float2 p1 = unpack2(acc[ww][1]);
            float4 r;
            r.x = expf(p0.x); r.y = expf(p0.y);
            r.z = expf(p1.x); r.w = expf(p1.y);
            if (kq == 15) { r.z = TINYV; r.w = TINYV; }   // tags 62 (EOS), 63 (BOS)
            *(float4*)&g_Bt[(size_t)w * KTAGS + kq * 4] = r;
        }
    }
}

// ---------------------------------------------------------------------------
// Kernel 3: forward scan, warp-private sentences, f32x2 FMA, no __syncthreads
// in the loop. Lane = s*8 + jq: 4 sentences x 8 tag-octets per warp.
// ---------------------------------------------------------------------------
__global__ __launch_bounds__(128, 1) void crf_scan_kernel(
        const int* __restrict__ words, float* __restrict__ out) {
    __shared__ __align__(16) float sA[KTAGS * KTAGS];                 // 16 KB
    __shared__ __align__(16) float sAlpha[NWARP][2][SPW][ASTR];      // 8.7 KB
    __shared__ int sW[SPB * WSTR];                                   // 16.4 KB

    int tid  = threadIdx.x;
    int warp = tid >> 5;
    int lane = tid & 31;
    int s    = lane >> 3;       // 0..3 local sentence within warp
    int jq   = lane & 7;        // 0..7 tag-octet
    int s0   = blockIdx.x * SPB;
    int sloc = warp * SPW + s;  // 0..15 sentence within CTA

    for (int idx = tid; idx < KTAGS * KTAGS; idx += 128) sA[idx] = g_A[idx];
    for (int idx = tid; idx < SPB * TLEN; idx += 128) {
        int ss = idx >> 8, t = idx & (TLEN - 1);
        sW[ss * WSTR + t] = words[(size_t)(s0 + ss) * TLEN + t];
    }
    __syncthreads();

    // alpha0: one-hot at BOS (tag 63 = octet 7, element 7)
    {
        float v[8] = {0, 0, 0, 0, 0, 0, 0, 0};
        if (jq == 7) v[7] = 1.0f;
        float* dst = &sAlpha[warp][0][s][jq << 3];
        *(float4*)dst       = make_float4(v[0], v[1], v[2], v[3]);
        *(float4*)(dst + 4) = make_float4(v[4], v[5], v[6], v[7]);
    }
    __syncwarp();

    const float* Ab = sA + (jq << 3);
    const int*   wr = sW + sloc * WSTR;

    // prefetch emissions for t=1
    int w = wr[1];
    const ulonglong2* br = (const ulonglong2*)(g_Bt + ((size_t)w << 6) + (jq << 3));
    ulonglong2 e01 = br[0];   // tags jq*8 .. +3
    ulonglong2 e23 = br[1];   // tags jq*8+4 .. +7

    int p = 0;
    for (int t = 1; t <= TLEN - 2; ++t) {
        // prefetch next step's emissions
        ulonglong2 n01, n23;
        if (t < TLEN - 2) {
            int wn = wr[t + 1];
            const ulonglong2* bn = (const ulonglong2*)(g_Bt + ((size_t)wn << 6) + (jq << 3));
            n01 = bn[0]; n23 = bn[1];
        }

        const float* al = sAlpha[warp][p][s];
        u64 acc0 = 0ull, acc1 = 0ull, acc2 = 0ull, acc3 = 0ull;

#pragma unroll 8
        for (int i = 0; i < KTAGS; i += 4) {
            float4 av = *(const float4*)(al + i);
#pragma unroll
            for (int ii = 0; ii < 4; ii++) {
                float a = (ii == 0) ? av.x : (ii == 1) ? av.y : (ii == 2) ? av.z : av.w;
                u64 ap = pack2(a, a);
                const ulonglong2* Ar = (const ulonglong2*)(Ab + ((i + ii) << 6));
                ulonglong2 A01 = Ar[0];   // cols jq*8 .. +3
                acc0 = fma2(ap, A01.x, acc0);
                acc1 = fma2(ap, A01.y, acc1);
                ulonglong2 A23 = ((const ulonglong2*)(Ab + ((i + ii) << 6) + 4))[0];
                acc2 = fma2(ap, A23.x, acc2);
                acc3 = fma2(ap, A23.y, acc3);
            }
        }

        // multiply by emissions, store new alpha
        u64 r0 = mul2(acc0, e01.x);
        u64 r1 = mul2(acc1, e01.y);
        u64 r2 = mul2(acc2, e23.x);
        u64 r3 = mul2(acc3, e23.y);
        ulonglong2* dst = (ulonglong2*)&sAlpha[warp][p ^ 1][s][jq << 3];
        dst[0] = make_ulonglong2(r0, r1);
        dst[1] = make_ulonglong2(r2, r3);

        e01 = n01; e23 = n23;
        __syncwarp();
        p ^= 1;
    }

    // final transition into EOS: z = alpha @ A'[:,EOS]
    {
        const float* al = sAlpha[warp][p][s];
        float z = 0.0f;
#pragma unroll
        for (int c = 0; c < 8; c++) {
            int i = (jq << 3) + c;
            z += al[i] * sA[i * KTAGS + EOS_TAG];
        }
#pragma unroll
        for (int off = 4; off; off >>= 1)
            z += __shfl_xor_sync(0xffffffffu, z, off);
        if (jq == 0) {
            // + 255 * log(64) = 1530 * ln2 (fixed-scaling compensation)
            out[s0 + sloc] = logf(z) + 1060.5151862567153f;
        }
    }
}

// ---------------------------------------------------------------------------
extern "C" void kernel_launch(void* const* d_in, const int* in_sizes, int n_in,
                              void* d_out, int out_size) {
    const int*   words  = nullptr;
    const float* ThetaB = nullptr;
    const float* WA     = nullptr;
    const float* E      = nullptr;
    for (int i = 0; i < n_in; i++) {
        switch (in_sizes[i]) {
            case BATCHN * TLEN:   words  = (const int*)d_in[i];   break;
            case KTAGS * DDIM:    ThetaB = (const float*)d_in[i]; break;
            case KTAGS * KTAGS:   WA     = (const float*)d_in[i]; break;
            case NV * DDIM:       E      = (const float*)d_in[i]; break;
        }
    }
    float* out = (float*)d_out;

    prep_A_kernel<<<16, 256>>>(WA);
    emit_table_kernel<<<(NV + 63) / 64, 256>>>(ThetaB, E);
    crf_scan_kernel<<<BATCHN / SPB, 128>>>(words, out);
}

// round 3
// speedup vs baseline: 2.6095x; 2.6095x over previous
#include <cuda_runtime.h>
#include <math.h>

#define KTAGS 64
#define DDIM  128
#define VWORDS 50000
#define NV   (VWORDS + 2)
#define BATCHN 2048
#define TLEN 256
#define BOS_TAG 63
#define EOS_TAG 62
#define TINYV 1e-45f

#define NWARP 4
#define SPW   4                 // sentences per warp
#define SPB   (NWARP * SPW)     // 16 sentences per CTA
#define ASTR  68
#define WSTR  257

typedef unsigned long long u64;

__device__ __forceinline__ u64 pack2(float lo, float hi) {
    u64 r; asm("mov.b64 %0,{%1,%2};" : "=l"(r) : "f"(lo), "f"(hi)); return r;
}
__device__ __forceinline__ u64 fma2(u64 a, u64 b, u64 c) {
    u64 d; asm("fma.rn.f32x2 %0,%1,%2,%3;" : "=l"(d) : "l"(a), "l"(b), "l"(c)); return d;
}
__device__ __forceinline__ u64 mul2(u64 a, u64 b) {
    u64 d; asm("mul.rn.f32x2 %0,%1,%2;" : "=l"(d) : "l"(a), "l"(b)); return d;
}
__device__ __forceinline__ float2 unpack2(u64 v) {
    float2 f; asm("mov.b64 {%0,%1},%2;" : "=f"(f.x), "=f"(f.y) : "l"(v)); return f;
}

// Scratch (static device globals; no dynamic allocation)
__device__ float g_A[KTAGS * KTAGS];               // A' = exp(WA)/64, col BOS zeroed
__device__ float g_Bt[(size_t)NV * KTAGS];         // emission table, word-major [w][k]

// ---------------------------------------------------------------------------
// Kernel 1: A'[i][j] = exp(WA[i][j]) / 64, A'[:,BOS] = 0
// ---------------------------------------------------------------------------
__global__ void prep_A_kernel(const float* __restrict__ WA) {
    int idx = blockIdx.x * blockDim.x + threadIdx.x;
    if (idx < KTAGS * KTAGS) {
        int j = idx & (KTAGS - 1);
        g_A[idx] = (j == BOS_TAG) ? 0.0f : expf(WA[idx]) * (1.0f / 64.0f);
    }
}

// ---------------------------------------------------------------------------
// Kernel 2: emission table g_Bt[w][k] = exp(dot(ThetaB[k,:], E[w,:]))
// ---------------------------------------------------------------------------
__global__ __launch_bounds__(256) void emit_table_kernel(
        const float* __restrict__ ThetaB, const float* __restrict__ E) {
    __shared__ __align__(16) float sE[64 * 65];
    __shared__ __align__(16) float sTh[64 * ASTR];

    int tid = threadIdx.x;
    int wq  = tid & 15;
    int kq  = tid >> 4;
    int w0  = blockIdx.x * 64;

    u64 acc[4][2];
#pragma unroll
    for (int a = 0; a < 4; a++) { acc[a][0] = 0ull; acc[a][1] = 0ull; }

    for (int dc = 0; dc < 2; dc++) {
        for (int idx = tid; idx < 64 * 64; idx += 256) {
            int k = idx >> 6, dl = idx & 63;
            sTh[dl * ASTR + k] = ThetaB[k * DDIM + dc * 64 + dl];
        }
        for (int idx = tid; idx < 64 * 64; idx += 256) {
            int w = idx >> 6, dl = idx & 63;
            int wg = w0 + w;
            sE[w * 65 + dl] = (wg < NV) ? E[(size_t)wg * DDIM + dc * 64 + dl] : 0.0f;
        }
        __syncthreads();

#pragma unroll 8
        for (int dl = 0; dl < 64; dl++) {
            ulonglong2 th = *(const ulonglong2*)&sTh[dl * ASTR + kq * 4];
#pragma unroll
            for (int ww = 0; ww < 4; ww++) {
                float e = sE[(wq * 4 + ww) * 65 + dl];
                u64 ep = pack2(e, e);
                acc[ww][0] = fma2(ep, th.x, acc[ww][0]);
                acc[ww][1] = fma2(ep, th.y, acc[ww][1]);
            }
        }
        __syncthreads();
    }

#pragma unroll
    for (int ww = 0; ww < 4; ww++) {
        int w = w0 + wq * 4 + ww;
        if (w < NV) {
            float2 p0 = unpack2(acc[ww][0]);
            float2 p1 = unpack2(acc[ww][1]);
            float4 r;
            r.x = expf(p0.x); r.y = expf(p0.y);
            r.z = expf(p1.x); r.w = expf(p1.y);
            if (kq == 15) { r.z = TINYV; r.w = TINYV; }
            *(float4*)&g_Bt[(size_t)w * KTAGS + kq * 4] = r;
        }
    }
}

// ---------------------------------------------------------------------------
// Kernel 3: forward scan. A register-resident: lane j holds A[:, 2j:2j+2]
// as 64 f32x2 regs. Alpha round-trips per step through smem as DUPLICATED
// pairs (a,a) so fma2 consumes broadcast LDS.128 with no packing. Per warp:
// 4 sentences share the A registers. Warp-private; one __syncwarp per step.
// ---------------------------------------------------------------------------
__global__ __launch_bounds__(128, 1) void crf_scan_kernel(
        const int* __restrict__ words, float* __restrict__ out) {
    // dup alpha: [warp][buf][sentence][i] = (a_i, a_i)
    __shared__ __align__(16) u64 sDup[NWARP][2][SPW][KTAGS];   // 16 KB
    __shared__ int sW[SPB * WSTR];                              // ~16.4 KB

    int tid  = threadIdx.x;
    int warp = tid >> 5;
    int lane = tid & 31;
    int s0   = blockIdx.x * SPB;

    // words -> smem
    for (int idx = tid; idx < SPB * TLEN; idx += 128) {
        int ss = idx >> 8, t = idx & (TLEN - 1);
        sW[ss * WSTR + t] = words[(size_t)(s0 + ss) * TLEN + t];
    }

    // A columns (2*lane, 2*lane+1) into registers: 64 packed f32x2
    u64 A_r[KTAGS];
#pragma unroll
    for (int i = 0; i < KTAGS; i++)
        A_r[i] = __ldg(((const u64*)g_A) + i * 32 + lane);

    // EOS column entries for this lane's two tags
    float eosL = __ldg(&g_A[(2 * lane) * KTAGS + EOS_TAG]);
    float eosH = __ldg(&g_A[(2 * lane + 1) * KTAGS + EOS_TAG]);

    // init alpha0 dup buffer: all zero, entry 63 (BOS) = (1,1)
#pragma unroll
    for (int s = 0; s < SPW; s++) {
        sDup[warp][0][s][2 * lane]     = 0ull;
        sDup[warp][0][s][2 * lane + 1] = 0ull;
    }
    __syncwarp();
    if (lane == 31) {
#pragma unroll
        for (int s = 0; s < SPW; s++)
            sDup[warp][0][s][BOS_TAG] = pack2(1.0f, 1.0f);
    }
    __syncthreads();   // also covers sW

    const int* wr = sW + (warp * SPW) * WSTR;

    // prefetch emissions for t=1: lane's tag pair for each sentence
    u64 e[SPW];
#pragma unroll
    for (int s = 0; s < SPW; s++) {
        int w = wr[s * WSTR + 1];
        e[s] = __ldg(((const u64*)g_Bt) + ((size_t)w << 5) + lane);
    }

    int p = 0;
    for (int t = 1; t <= TLEN - 2; ++t) {
        // prefetch next step's emissions (t=254 reads pos 255: valid memory, unused)
        u64 en[SPW];
#pragma unroll
        for (int s = 0; s < SPW; s++) {
            int wn = wr[s * WSTR + t + 1];
            en[s] = __ldg(((const u64*)g_Bt) + ((size_t)wn << 5) + lane);
        }

        u64 acc[SPW];
#pragma unroll
        for (int s = 0; s < SPW; s++) acc[s] = 0ull;

        const u64* dp = &sDup[warp][p][0][0];
#pragma unroll
        for (int i = 0; i < KTAGS; i += 2) {
#pragma unroll
            for (int s = 0; s < SPW; s++) {
                ulonglong2 d = *(const ulonglong2*)(dp + s * KTAGS + i);  // {dup a_i, dup a_i+1}
                acc[s] = fma2(d.x, A_r[i],     acc[s]);
                acc[s] = fma2(d.y, A_r[i + 1], acc[s]);
            }
        }

        // emission multiply + duplicated store for next step
#pragma unroll
        for (int s = 0; s < SPW; s++) {
            u64 r = mul2(acc[s], e[s]);
            float2 f = unpack2(r);
            float4 st = make_float4(f.x, f.x, f.y, f.y);
            *(float4*)&sDup[warp][p ^ 1][s][2 * lane] = st;
            e[s] = en[s];
        }
        __syncwarp();
        p ^= 1;
    }

    // final transition into EOS
#pragma unroll
    for (int s = 0; s < SPW; s++) {
        float aL = *(const float*)&sDup[warp][p][s][2 * lane];
        float aH = *(const float*)&sDup[warp][p][s][2 * lane + 1];
        float z = aL * eosL + aH * eosH;
#pragma unroll
        for (int off = 16; off; off >>= 1)
            z += __shfl_xor_sync(0xffffffffu, z, off);
        if (lane == 0) {
            // + 255 * log(64) = 1530 * ln2 (fixed-scaling compensation)
            out[s0 + warp * SPW + s] = logf(z) + 1060.5151862567153f;
        }
    }
}

// ---------------------------------------------------------------------------
extern "C" void kernel_launch(void* const* d_in, const int* in_sizes, int n_in,
                              void* d_out, int out_size) {
    const int*   words  = nullptr;
    const float* ThetaB = nullptr;
    const float* WA     = nullptr;
    const float* E      = nullptr;
    for (int i = 0; i < n_in; i++) {
        switch (in_sizes[i]) {
            case BATCHN * TLEN:   words  = (const int*)d_in[i];   break;
            case KTAGS * DDIM:    ThetaB = (const float*)d_in[i]; break;
            case KTAGS * KTAGS:   WA     = (const float*)d_in[i]; break;
            case NV * DDIM:       E      = (const float*)d_in[i]; break;
        }
    }
    float* out = (float*)d_out;

    prep_A_kernel<<<16, 256>>>(WA);
    emit_table_kernel<<<(NV + 63) / 64, 256>>>(ThetaB, E);
    crf_scan_kernel<<<BATCHN / SPB, 128>>>(words, out);
}

// round 4
// speedup vs baseline: 3.1974x; 1.2253x over previous
#include <cuda_runtime.h>
#include <math.h>

#define KTAGS 64
#define DDIM  128
#define VWORDS 50000
#define NV   (VWORDS + 2)
#define BATCHN 2048
#define TLEN 256
#define BOS_TAG 63
#define EOS_TAG 62
#define TINYV 1e-45f

#define NWARP 4
#define SPW   2                 // sentences per warp
#define SPB   (NWARP * SPW)     // 8 sentences per CTA
#define ASTR  68
#define WSTR  257

typedef unsigned long long u64;

__device__ __forceinline__ u64 pack2(float lo, float hi) {
    u64 r; asm("mov.b64 %0,{%1,%2};" : "=l"(r) : "f"(lo), "f"(hi)); return r;
}
__device__ __forceinline__ u64 fma2(u64 a, u64 b, u64 c) {
    u64 d; asm("fma.rn.f32x2 %0,%1,%2,%3;" : "=l"(d) : "l"(a), "l"(b), "l"(c)); return d;
}
__device__ __forceinline__ u64 mul2(u64 a, u64 b) {
    u64 d; asm("mul.rn.f32x2 %0,%1,%2;" : "=l"(d) : "l"(a), "l"(b)); return d;
}
__device__ __forceinline__ float2 unpack2(u64 v) {
    float2 f; asm("mov.b64 {%0,%1},%2;" : "=f"(f.x), "=f"(f.y) : "l"(v)); return f;
}

// Scratch (static device global; no dynamic allocation)
__device__ float g_Bt[(size_t)NV * KTAGS];         // emission table, word-major [w][k]

// ---------------------------------------------------------------------------
// Kernel 1: emission table g_Bt[w][k] = exp(dot(ThetaB[k,:], E[w,:]))
// ---------------------------------------------------------------------------
__global__ __launch_bounds__(256) void emit_table_kernel(
        const float* __restrict__ ThetaB, const float* __restrict__ E) {
    __shared__ __align__(16) float sE[64 * 65];
    __shared__ __align__(16) float sTh[64 * ASTR];

    int tid = threadIdx.x;
    int wq  = tid & 15;
    int kq  = tid >> 4;
    int w0  = blockIdx.x * 64;

    u64 acc[4][2];
#pragma unroll
    for (int a = 0; a < 4; a++) { acc[a][0] = 0ull; acc[a][1] = 0ull; }

    for (int dc = 0; dc < 2; dc++) {
        for (int idx = tid; idx < 64 * 64; idx += 256) {
            int k = idx >> 6, dl = idx & 63;
            sTh[dl * ASTR + k] = ThetaB[k * DDIM + dc * 64 + dl];
        }
        for (int idx = tid; idx < 64 * 64; idx += 256) {
            int w = idx >> 6, dl = idx & 63;
            int wg = w0 + w;
            sE[w * 65 + dl] = (wg < NV) ? E[(size_t)wg * DDIM + dc * 64 + dl] : 0.0f;
        }
        __syncthreads();

#pragma unroll 8
        for (int dl = 0; dl < 64; dl++) {
            ulonglong2 th = *(const ulonglong2*)&sTh[dl * ASTR + kq * 4];
#pragma unroll
            for (int ww = 0; ww < 4; ww++) {
                float e = sE[(wq * 4 + ww) * 65 + dl];
                u64 ep = pack2(e, e);
                acc[ww][0] = fma2(ep, th.x, acc[ww][0]);
                acc[ww][1] = fma2(ep, th.y, acc[ww][1]);
            }
        }
        __syncthreads();
    }

#pragma unroll
    for (int ww = 0; ww < 4; ww++) {
        int w = w0 + wq * 4 + ww;
        if (w < NV) {
            float2 p0 = unpack2(acc[ww][0]);
            float2 p1 = unpack2(acc[ww][1]);
            float4 r;
            r.x = expf(p0.x); r.y = expf(p0.y);
            r.z = expf(p1.x); r.w = expf(p1.y);
            if (kq == 15) { r.z = TINYV; r.w = TINYV; }
            *(float4*)&g_Bt[(size_t)w * KTAGS + kq * 4] = r;
        }
    }
}

// ---------------------------------------------------------------------------
// Kernel 2: forward scan. A' = exp(WA)/64 computed in-kernel, register-
// resident: lane j holds A'[:, 2j:2j+2] as 64 f32x2 regs. Alpha round-trips
// per step through smem as duplicated pairs (a,a) -> broadcast LDS.128 feeds
// fma2 directly. SPW=2 sentences/warp, occupancy 2 CTAs/SM (2 warps/SMSP)
// to hide LDS/LDG latency under the FFMA2 pipe floor.
// ---------------------------------------------------------------------------
__global__ __launch_bounds__(128, 2) void crf_scan_kernel(
        const float* __restrict__ WA,
        const int* __restrict__ words, float* __restrict__ out) {
    __shared__ __align__(16) u64 sDup[NWARP][2][SPW][KTAGS];   // 8 KB
    __shared__ int sW[SPB * WSTR];                              // 8.2 KB

    int tid  = threadIdx.x;
    int warp = tid >> 5;
    int lane = tid & 31;
    int s0   = blockIdx.x * SPB;

    // words -> smem
    for (int idx = tid; idx < SPB * TLEN; idx += 128) {
        int ss = idx >> 8, t = idx & (TLEN - 1);
        sW[ss * WSTR + t] = words[(size_t)(s0 + ss) * TLEN + t];
    }

    // A' columns (2*lane, 2*lane+1) into registers: A'[i][j] = exp(WA[i][j])/64,
    // column BOS_TAG (=63, i.e. lane 31 hi half) zeroed.
    u64 A_r[KTAGS];
#pragma unroll
    for (int i = 0; i < KTAGS; i++) {
        float lo = expf(__ldg(&WA[i * KTAGS + 2 * lane]))     * (1.0f / 64.0f);
        float hi = (2 * lane + 1 == BOS_TAG) ? 0.0f
                 : expf(__ldg(&WA[i * KTAGS + 2 * lane + 1])) * (1.0f / 64.0f);
        A_r[i] = pack2(lo, hi);
    }

    // EOS column entries for this lane's two tags: A'[2lane][EOS], A'[2lane+1][EOS]
    float eosL = expf(__ldg(&WA[(2 * lane)     * KTAGS + EOS_TAG])) * (1.0f / 64.0f);
    float eosH = expf(__ldg(&WA[(2 * lane + 1) * KTAGS + EOS_TAG])) * (1.0f / 64.0f);

    // init alpha0 dup buffer: all zero, entry 63 (BOS) = (1,1)
#pragma unroll
    for (int s = 0; s < SPW; s++) {
        sDup[warp][0][s][2 * lane]     = 0ull;
        sDup[warp][0][s][2 * lane + 1] = 0ull;
    }
    __syncwarp();
    if (lane == 31) {
#pragma unroll
        for (int s = 0; s < SPW; s++)
            sDup[warp][0][s][BOS_TAG] = pack2(1.0f, 1.0f);
    }
    __syncthreads();   // also covers sW

    const int* wr = sW + (warp * SPW) * WSTR;

    // prefetch emissions for t=1
    u64 e[SPW];
#pragma unroll
    for (int s = 0; s < SPW; s++) {
        int w = wr[s * WSTR + 1];
        e[s] = __ldg(((const u64*)g_Bt) + ((size_t)w << 5) + lane);
    }

    int p = 0;
    for (int t = 1; t <= TLEN - 2; ++t) {
        // prefetch next step's emissions (t=254 reads pos 255: valid, unused)
        u64 en[SPW];
#pragma unroll
        for (int s = 0; s < SPW; s++) {
            int wn = wr[s * WSTR + t + 1];
            en[s] = __ldg(((const u64*)g_Bt) + ((size_t)wn << 5) + lane);
        }

        u64 acc[SPW];
#pragma unroll
        for (int s = 0; s < SPW; s++) acc[s] = 0ull;

        const u64* dp = &sDup[warp][p][0][0];
#pragma unroll
        for (int i = 0; i < KTAGS; i += 2) {
#pragma unroll
            for (int s = 0; s < SPW; s++) {
                ulonglong2 d = *(const ulonglong2*)(dp + s * KTAGS + i);
                acc[s] = fma2(d.x, A_r[i],     acc[s]);
                acc[s] = fma2(d.y, A_r[i + 1], acc[s]);
            }
        }

        // emission multiply + duplicated store for next step
#pragma unroll
        for (int s = 0; s < SPW; s++) {
            u64 r = mul2(acc[s], e[s]);
            float2 f = unpack2(r);
            float4 st = make_float4(f.x, f.x, f.y, f.y);
            *(float4*)&sDup[warp][p ^ 1][s][2 * lane] = st;
            e[s] = en[s];
        }
        __syncwarp();
        p ^= 1;
    }

    // final transition into EOS
#pragma unroll
    for (int s = 0; s < SPW; s++) {
        float aL = *(const float*)&sDup[warp][p][s][2 * lane];
        float aH = *(const float*)&sDup[warp][p][s][2 * lane + 1];
        float z = aL * eosL + aH * eosH;
#pragma unroll
        for (int off = 16; off; off >>= 1)
            z += __shfl_xor_sync(0xffffffffu, z, off);
        if (lane == 0) {
            // + 255 * log(64) = 1530 * ln2 (fixed-scaling compensation)
            out[s0 + warp * SPW + s] = logf(z) + 1060.5151862567153f;
        }
    }
}

// ---------------------------------------------------------------------------
extern "C" void kernel_launch(void* const* d_in, const int* in_sizes, int n_in,
                              void* d_out, int out_size) {
    const int*   words  = nullptr;
    const float* ThetaB = nullptr;
    const float* WA     = nullptr;
    const float* E      = nullptr;
    for (int i = 0; i < n_in; i++) {
        switch (in_sizes[i]) {
            case BATCHN * TLEN:   words  = (const int*)d_in[i];   break;
            case KTAGS * DDIM:    ThetaB = (const float*)d_in[i]; break;
            case KTAGS * KTAGS:   WA     = (const float*)d_in[i]; break;
            case NV * DDIM:       E      = (const float*)d_in[i]; break;
        }
    }
    float* out = (float*)d_out;

    emit_table_kernel<<<(NV + 63) / 64, 256>>>(ThetaB, E);
    crf_scan_kernel<<<BATCHN / SPB, 128>>>(WA, words, out);
}

// round 5
// speedup vs baseline: 3.4191x; 1.0694x over previous
#include <cuda_runtime.h>
#include <math.h>

#define KTAGS 64
#define DDIM  128
#define VWORDS 50000
#define NV   (VWORDS + 2)
#define BATCHN 2048
#define TLEN 256
#define BOS_TAG 63
#define EOS_TAG 62
#define TINYV 1e-45f

#define NWARP 4
#define SPW   2                 // sentences per warp
#define SPB   (NWARP * SPW)     // 8 sentences per CTA
#define ASTR  68

typedef unsigned long long u64;

__device__ __forceinline__ u64 pack2(float lo, float hi) {
    u64 r; asm("mov.b64 %0,{%1,%2};" : "=l"(r) : "f"(lo), "f"(hi)); return r;
}
__device__ __forceinline__ u64 fma2(u64 a, u64 b, u64 c) {
    u64 d; asm("fma.rn.f32x2 %0,%1,%2,%3;" : "=l"(d) : "l"(a), "l"(b), "l"(c)); return d;
}
__device__ __forceinline__ u64 mul2(u64 a, u64 b) {
    u64 d; asm("mul.rn.f32x2 %0,%1,%2;" : "=l"(d) : "l"(a), "l"(b)); return d;
}
__device__ __forceinline__ float2 unpack2(u64 v) {
    float2 f; asm("mov.b64 {%0,%1},%2;" : "=f"(f.x), "=f"(f.y) : "l"(v)); return f;
}

// Scratch (static device global; no dynamic allocation)
__device__ float g_Bt[(size_t)NV * KTAGS];   // emission table, word-major [w][k]

// ---------------------------------------------------------------------------
// Kernel 1: emission table g_Bt[w][k] = exp(dot(ThetaB[k,:], E[w,:]))
// ---------------------------------------------------------------------------
__global__ __launch_bounds__(256) void emit_table_kernel(
        const float* __restrict__ ThetaB, const float* __restrict__ E) {
    __shared__ __align__(16) float sE[64 * 65];
    __shared__ __align__(16) float sTh[64 * ASTR];

    int tid = threadIdx.x;
    int wq  = tid & 15;
    int kq  = tid >> 4;
    int w0  = blockIdx.x * 64;

    u64 acc[4][2];
#pragma unroll
    for (int a = 0; a < 4; a++) { acc[a][0] = 0ull; acc[a][1] = 0ull; }

    for (int dc = 0; dc < 2; dc++) {
        for (int idx = tid; idx < 64 * 64; idx += 256) {
            int k = idx >> 6, dl = idx & 63;
            sTh[dl * ASTR + k] = ThetaB[k * DDIM + dc * 64 + dl];
        }
        for (int idx = tid; idx < 64 * 64; idx += 256) {
            int w = idx >> 6, dl = idx & 63;
            int wg = w0 + w;
            sE[w * 65 + dl] = (wg < NV) ? E[(size_t)wg * DDIM + dc * 64 + dl] : 0.0f;
        }
        __syncthreads();

#pragma unroll 8
        for (int dl = 0; dl < 64; dl++) {
            ulonglong2 th = *(const ulonglong2*)&sTh[dl * ASTR + kq * 4];
#pragma unroll
            for (int ww = 0; ww < 4; ww++) {
                float e = sE[(wq * 4 + ww) * 65 + dl];
                u64 ep = pack2(e, e);
                acc[ww][0] = fma2(ep, th.x, acc[ww][0]);
                acc[ww][1] = fma2(ep, th.y, acc[ww][1]);
            }
        }
        __syncthreads();
    }

#pragma unroll
    for (int ww = 0; ww < 4; ww++) {
        int w = w0 + wq * 4 + ww;
        if (w < NV) {
            float2 p0 = unpack2(acc[ww][0]);
            float2 p1 = unpack2(acc[ww][1]);
            float4 r;
            r.x = expf(p0.x); r.y = expf(p0.y);
            r.z = expf(p1.x); r.w = expf(p1.y);
            if (kq == 15) { r.z = TINYV; r.w = TINYV; }
            *(float4*)&g_Bt[(size_t)w * KTAGS + kq * 4] = r;
        }
    }
}

// ---------------------------------------------------------------------------
// Kernel 2: forward scan, dot-product f32x2 form.
// Lane l owns OUTPUT tags (2l, 2l+1). A' register layout: AL[i]/AH[i] hold
// (A'[2i][2l], A'[2i+1][2l]) / same for col 2l+1. Alpha lives in smem as
// natural packed pairs (a_2i, a_2i+1) -> broadcast LDS.128 feeds fma2 with
// NO duplication or packing. acc folds lo+hi once per step.
// ---------------------------------------------------------------------------
__global__ __launch_bounds__(128, 2) void crf_scan_kernel(
        const float* __restrict__ WA,
        const int* __restrict__ words, float* __restrict__ out) {
    __shared__ __align__(16) u64 sAl[NWARP][2][SPW][KTAGS / 2];  // 8 KB
    __shared__ int sWT[TLEN][SPB];                                // transposed words, 8 KB

    int tid  = threadIdx.x;
    int warp = tid >> 5;
    int lane = tid & 31;
    int s0   = blockIdx.x * SPB;

    // words -> smem transposed: sWT[t][s]
    for (int idx = tid; idx < SPB * TLEN; idx += 128) {
        int ss = idx >> 8, t = idx & (TLEN - 1);
        sWT[t][ss] = words[(size_t)(s0 + ss) * TLEN + t];
    }

    // A' into registers, dot-product layout.
    // AL[i] = (A'[2i][2l], A'[2i+1][2l]), AH[i] = same for column 2l+1.
    // A'[r][c] = exp(WA[r*64+c])/64 ; column BOS_TAG == 63 is zero.
    int jL = 2 * lane, jH = 2 * lane + 1;
    u64 AL[KTAGS / 2], AH[KTAGS / 2];
#pragma unroll
    for (int i = 0; i < KTAGS / 2; i++) {
        float l0 = expf(__ldg(&WA[(2 * i)     * KTAGS + jL])) * (1.0f / 64.0f);
        float l1 = expf(__ldg(&WA[(2 * i + 1) * KTAGS + jL])) * (1.0f / 64.0f);
        AL[i] = pack2(l0, l1);
        float h0, h1;
        if (jH == BOS_TAG) { h0 = 0.0f; h1 = 0.0f; }
        else {
            h0 = expf(__ldg(&WA[(2 * i)     * KTAGS + jH])) * (1.0f / 64.0f);
            h1 = expf(__ldg(&WA[(2 * i + 1) * KTAGS + jH])) * (1.0f / 64.0f);
        }
        AH[i] = pack2(h0, h1);
    }

    // EOS column entries for this lane's two tags
    float eosL = expf(__ldg(&WA[jL * KTAGS + EOS_TAG])) * (1.0f / 64.0f);
    float eosH = expf(__ldg(&WA[jH * KTAGS + EOS_TAG])) * (1.0f / 64.0f);

    // alpha0: pair 31 = (alpha[62], alpha[63]) = (0, 1); all else 0
#pragma unroll
    for (int s = 0; s < SPW; s++)
        sAl[warp][0][s][lane] = (lane == 31) ? pack2(0.0f, 1.0f) : 0ull;
    __syncthreads();   // covers sWT too

    int sbase = warp * SPW;

    // prefetch emissions for t=1
    u64 e[SPW];
#pragma unroll
    for (int s = 0; s < SPW; s++) {
        int w = sWT[1][sbase + s];
        e[s] = __ldg(((const u64*)g_Bt) + ((size_t)w << 5) + lane);
    }

    int p = 0;
    for (int t = 1; t <= TLEN - 2; ++t) {
        // prefetch next step's emissions (t=254 reads pos 255: valid, unused)
        u64 en[SPW];
#pragma unroll
        for (int s = 0; s < SPW; s++) {
            int wn = sWT[t + 1][sbase + s];
            en[s] = __ldg(((const u64*)g_Bt) + ((size_t)wn << 5) + lane);
        }

        u64 accL[SPW], accH[SPW];
#pragma unroll
        for (int s = 0; s < SPW; s++) { accL[s] = 0ull; accH[s] = 0ull; }

#pragma unroll
        for (int i = 0; i < KTAGS / 2; i += 2) {
#pragma unroll
            for (int s = 0; s < SPW; s++) {
                ulonglong2 v = *(const ulonglong2*)&sAl[warp][p][s][i];
                accL[s] = fma2(v.x, AL[i],     accL[s]);
                accH[s] = fma2(v.x, AH[i],     accH[s]);
                accL[s] = fma2(v.y, AL[i + 1], accL[s]);
                accH[s] = fma2(v.y, AH[i + 1], accH[s]);
            }
        }

        // fold lo+hi, multiply by emissions, store packed pair
#pragma unroll
        for (int s = 0; s < SPW; s++) {
            float2 fL = unpack2(accL[s]);
            float2 fH = unpack2(accH[s]);
            u64 r = mul2(pack2(fL.x + fL.y, fH.x + fH.y), e[s]);
            sAl[warp][p ^ 1][s][lane] = r;
            e[s] = en[s];
        }
        __syncwarp();
        p ^= 1;
    }

    // final transition into EOS
#pragma unroll
    for (int s = 0; s < SPW; s++) {
        float2 a = unpack2(sAl[warp][p][s][lane]);
        float z = a.x * eosL + a.y * eosH;
#pragma unroll
        for (int off = 16; off; off >>= 1)
            z += __shfl_xor_sync(0xffffffffu, z, off);
        if (lane == 0) {
            // + 255 * log(64) = 1530 * ln2 (fixed-scaling compensation)
            out[s0 + sbase + s] = logf(z) + 1060.5151862567153f;
        }
    }
}

// ---------------------------------------------------------------------------
extern "C" void kernel_launch(void* const* d_in, const int* in_sizes, int n_in,
                              void* d_out, int out_size) {
    const int*   words  = nullptr;
    const float* ThetaB = nullptr;
    const float* WA     = nullptr;
    const float* E      = nullptr;
    for (int i = 0; i < n_in; i++) {
        switch (in_sizes[i]) {
            case BATCHN * TLEN:   words  = (const int*)d_in[i];   break;
            case KTAGS * DDIM:    ThetaB = (const float*)d_in[i]; break;
            case KTAGS * KTAGS:   WA     = (const float*)d_in[i]; break;
            case NV * DDIM:       E      = (const float*)d_in[i]; break;
        }
    }
    float* out = (float*)d_out;

    emit_table_kernel<<<(NV + 63) / 64, 256>>>(ThetaB, E);
    crf_scan_kernel<<<BATCHN / SPB, 128>>>(WA, words, out);
}